// round 11
// baseline (speedup 1.0000x reference)
#include <cuda_runtime.h>
#include <cuda_fp16.h>
#include <mma.h>

using namespace nvcuda;

// Problem constants (shapes fixed by the reference).
#define NMAX   100000
#define NEMAX  1600000
#define FEAT   64
#define SCAN_T 256

// ---------------- device scratch (no allocations allowed) ----------------
// g_t16 padded by 128 rows: last GEMM block stores a full 128-row tile unguarded.
__device__ __half   g_t16[(NMAX + 128) * FEAT];  // fp16 features for gather
__device__ float    g_h[NMAX * FEAT];
__device__ unsigned g_degout[NMAX];
__device__ unsigned g_degin[NMAX];
__device__ float    g_iso[NMAX];          // D_out^{-1/2}
__device__ float    g_isi[NMAX];          // D_in^{-1/2}
__device__ int      g_rowstart[NMAX + 1]; // CSR row offsets (by dst)
__device__ int      g_cursor[NMAX];       // fill cursors
__device__ int      g_csr[NEMAX];         // src ids grouped by dst
__device__ int      g_blksum[512];        // scan block totals

// ---------------- degree / normalizer kernels ----------------

__global__ void zero_deg_kernel(int nn) {
    int i = blockIdx.x * blockDim.x + threadIdx.x;
    if (i < nn) { g_degout[i] = 0u; g_degin[i] = 0u; g_cursor[i] = 0; }
    if (i == 0) g_rowstart[0] = 0;
}

__global__ void deg_kernel(const int* __restrict__ src, const int* __restrict__ dst, int ne) {
    int e = blockIdx.x * blockDim.x + threadIdx.x;
    if (e < ne) {
        atomicAdd(&g_degout[src[e]], 1u);
        atomicAdd(&g_degin[dst[e]], 1u);
    }
}

__global__ void inv_kernel(int nn) {
    int i = blockIdx.x * blockDim.x + threadIdx.x;
    if (i < nn) {
        g_iso[i] = rsqrtf(fmaxf((float)g_degout[i], 1.0f));
        g_isi[i] = rsqrtf(fmaxf((float)g_degin[i], 1.0f));
    }
}

// ---------------- prefix-sum (exclusive) over in-degrees -> g_rowstart ----------------
__global__ void scanA_kernel(int nn) {
    __shared__ int sh[SCAN_T];
    int tid = threadIdx.x;
    int i = blockIdx.x * SCAN_T + tid;
    int v = (i < nn) ? (int)g_degin[i] : 0;
    sh[tid] = v;
    __syncthreads();
#pragma unroll
    for (int off = 1; off < SCAN_T; off <<= 1) {
        int t = (tid >= off) ? sh[tid - off] : 0;
        __syncthreads();
        sh[tid] += t;
        __syncthreads();
    }
    if (i < nn) g_rowstart[i + 1] = sh[tid];
    if (tid == SCAN_T - 1) g_blksum[blockIdx.x] = sh[tid];
}

__global__ void scanB_kernel(int nb) {
    __shared__ int sh[512];
    int tid = threadIdx.x;
    sh[tid] = (tid < nb) ? g_blksum[tid] : 0;
    __syncthreads();
#pragma unroll
    for (int off = 1; off < 512; off <<= 1) {
        int t = (tid >= off) ? sh[tid - off] : 0;
        __syncthreads();
        sh[tid] += t;
        __syncthreads();
    }
    g_blksum[tid] = sh[tid];
}

__global__ void scanC_kernel(int nn) {
    int i = blockIdx.x * SCAN_T + threadIdx.x;
    if (i < nn && blockIdx.x > 0) g_rowstart[i + 1] += g_blksum[blockIdx.x - 1];
}

__global__ void csr_fill_kernel(const int* __restrict__ src, const int* __restrict__ dst, int ne) {
    int e = blockIdx.x * blockDim.x + threadIdx.x;
    if (e < ne) {
        int d = dst[e];
        int pos = atomicAdd(&g_cursor[d], 1);
        g_csr[g_rowstart[d] + pos] = src[e];
    }
}

// ---------------- dense transform via TF32 tensor cores ----------------
// T = (X * iso) @ W -> fp16 g_t16 directly (fp32 staged only through smem).
// Block tile: 128 nodes x 64 cols, 256 threads (8 warps).
template <int K>
__global__ void gemm_mma_kernel(const float* __restrict__ X, const float* __restrict__ W, int nn) {
    constexpr int KC  = 32;
    constexpr int XLD = KC + 4;       // 36 floats
    constexpr int WLD = FEAT + 4;     // 68 floats
    constexpr int SLD = FEAT + 4;     // stage leading dim (mult of 4 for wmma)

    // Union: mainloop tiles (27.1 KB) vs fp32 stage tile (34.8 KB).
    __shared__ __align__(16) char smem_raw[128 * SLD * sizeof(float)];
    float (*Ws)[WLD] = reinterpret_cast<float (*)[WLD]>(smem_raw);
    float (*Xs)[XLD] = reinterpret_cast<float (*)[XLD]>(smem_raw + KC * WLD * sizeof(float));
    float (*St)[SLD] = reinterpret_cast<float (*)[SLD]>(smem_raw);

    const int tid = threadIdx.x;
    const int wid = tid >> 5;
    const int warp_row = wid >> 1;    // 0..3 -> 32-row band
    const int warp_col = wid & 1;     // 0..1 -> 32-col band
    const int nodeBase = blockIdx.x * 128;

    wmma::fragment<wmma::accumulator, 16, 16, 8, float> acc[2][2];
#pragma unroll
    for (int r = 0; r < 2; r++)
#pragma unroll
        for (int c = 0; c < 2; c++) wmma::fill_fragment(acc[r][c], 0.0f);

    for (int k0 = 0; k0 < K; k0 += KC) {
#pragma unroll
        for (int i = tid; i < KC * (FEAT / 4); i += 256) {
            int r = i >> 4, c4 = i & 15;
            float4 v = *reinterpret_cast<const float4*>(&W[(k0 + r) * FEAT + c4 * 4]);
            *reinterpret_cast<float4*>(&Ws[r][c4 * 4]) = v;
        }
#pragma unroll
        for (int i = tid; i < 128 * (KC / 4); i += 256) {
            int r = i / (KC / 4), c4 = i % (KC / 4);
            int node = nodeBase + r;
            float4 v = make_float4(0.f, 0.f, 0.f, 0.f);
            if (node < nn) {
                v = *reinterpret_cast<const float4*>(&X[(size_t)node * K + k0 + c4 * 4]);
                float s = g_iso[node];
                v.x *= s; v.y *= s; v.z *= s; v.w *= s;
            }
            *reinterpret_cast<float4*>(&Xs[r][c4 * 4]) = v;
        }
        __syncthreads();

#pragma unroll
        for (int kk = 0; kk < KC; kk += 8) {
            wmma::fragment<wmma::matrix_a, 16, 16, 8, wmma::precision::tf32, wmma::row_major> a[2];
            wmma::fragment<wmma::matrix_b, 16, 16, 8, wmma::precision::tf32, wmma::row_major> b[2];
#pragma unroll
            for (int r = 0; r < 2; r++) {
                wmma::load_matrix_sync(a[r], &Xs[warp_row * 32 + r * 16][kk], XLD);
#pragma unroll
                for (int t = 0; t < a[r].num_elements; t++)
                    a[r].x[t] = wmma::__float_to_tf32(a[r].x[t]);
            }
#pragma unroll
            for (int c = 0; c < 2; c++) {
                wmma::load_matrix_sync(b[c], &Ws[kk][warp_col * 32 + c * 16], WLD);
#pragma unroll
                for (int t = 0; t < b[c].num_elements; t++)
                    b[c].x[t] = wmma::__float_to_tf32(b[c].x[t]);
            }
#pragma unroll
            for (int r = 0; r < 2; r++)
#pragma unroll
                for (int c = 0; c < 2; c++)
                    wmma::mma_sync(acc[r][c], a[r], b[c], acc[r][c]);
        }
        __syncthreads();
    }

    // Epilogue: fp32 tile -> smem stage -> packed fp16 global stores.
#pragma unroll
    for (int r = 0; r < 2; r++)
#pragma unroll
        for (int c = 0; c < 2; c++)
            wmma::store_matrix_sync(&St[warp_row * 32 + r * 16][warp_col * 32 + c * 16],
                                    acc[r][c], SLD, wmma::mem_row_major);
    __syncthreads();

#pragma unroll
    for (int i = tid; i < 128 * (FEAT / 8); i += 256) {
        int r = i >> 3;
        int c8 = (i & 7) * 8;
        float4 f0 = *reinterpret_cast<float4*>(&St[r][c8]);
        float4 f1 = *reinterpret_cast<float4*>(&St[r][c8 + 4]);
        __half2 h0 = __floats2half2_rn(f0.x, f0.y);
        __half2 h1 = __floats2half2_rn(f0.z, f0.w);
        __half2 h2 = __floats2half2_rn(f1.x, f1.y);
        __half2 h3 = __floats2half2_rn(f1.z, f1.w);
        uint4 pack;
        pack.x = *reinterpret_cast<unsigned*>(&h0);
        pack.y = *reinterpret_cast<unsigned*>(&h1);
        pack.z = *reinterpret_cast<unsigned*>(&h2);
        pack.w = *reinterpret_cast<unsigned*>(&h3);
        *reinterpret_cast<uint4*>(&g_t16[(size_t)(nodeBase + r) * FEAT + c8]) = pack;
    }
}

// ---------------- CSR gather + finalize ----------------
// 16 lanes per node; each lane owns 4 half columns (8 B per edge).
// Edge indices are loaded coalesced (one per lane per 16 edges) and
// broadcast via shuffle -> ~17 LDG issues per edge instead of 32.
template <int RELU>
__global__ void gather_kernel(const float* __restrict__ b, float* __restrict__ out, int nn) {
    int idx = blockIdx.x * blockDim.x + threadIdx.x;
    int node = idx >> 4;
    int lane = idx & 15;
    int c = lane << 2;                // half-column base (0,4,...,60)
    if (node >= nn) return;           // never taken (grid exact), keeps safety

    int rs = g_rowstart[node];
    int re = g_rowstart[node + 1];

    float acc0 = 0.f, acc1 = 0.f, acc2 = 0.f, acc3 = 0.f;

    for (int p0 = rs; p0 < re; p0 += 16) {
        int chunk = re - p0;
        if (chunk > 16) chunk = 16;
        int myIdx = 0;
        if (lane < chunk) myIdx = __ldg(&g_csr[p0 + lane]);   // coalesced

#pragma unroll 4
        for (int j = 0; j < chunk; ++j) {
            int s = __shfl_sync(0xffffffffu, myIdx, j, 16);   // broadcast within 16-lane group
            uint2 u = __ldg(reinterpret_cast<const uint2*>(&g_t16[(size_t)s * FEAT + c]));
            float2 f0 = __half22float2(*reinterpret_cast<__half2*>(&u.x));
            float2 f1 = __half22float2(*reinterpret_cast<__half2*>(&u.y));
            acc0 += f0.x; acc1 += f0.y; acc2 += f1.x; acc3 += f1.y;
        }
    }

    float sN = g_isi[node];
    float4 bb = *reinterpret_cast<const float4*>(&b[c]);
    float4 o;
    o.x = acc0 * sN + bb.x;
    o.y = acc1 * sN + bb.y;
    o.z = acc2 * sN + bb.z;
    o.w = acc3 * sN + bb.w;
    if (RELU) {
        o.x = fmaxf(o.x, 0.f); o.y = fmaxf(o.y, 0.f);
        o.z = fmaxf(o.z, 0.f); o.w = fmaxf(o.w, 0.f);
    }
    *reinterpret_cast<float4*>(&out[(size_t)node * FEAT + c]) = o;
}

// ---------------- launch ----------------
extern "C" void kernel_launch(void* const* d_in, const int* in_sizes, int n_in,
                              void* d_out, int out_size) {
    const float* x   = (const float*)d_in[0];
    const int*   src = (const int*)d_in[1];
    const int*   dst = (const int*)d_in[2];
    const float* W1  = (const float*)d_in[3];
    const float* b1  = (const float*)d_in[4];
    const float* W2  = (const float*)d_in[5];
    const float* b2  = (const float*)d_in[6];
    const float* W3  = (const float*)d_in[7];
    const float* b3  = (const float*)d_in[8];
    float* out = (float*)d_out;

    const int nn = in_sizes[0] / 128;   // 100000
    const int ne = in_sizes[1];         // 1600000

    static float* h_ptr = nullptr;
    if (h_ptr == nullptr) {
        cudaGetSymbolAddress((void**)&h_ptr, g_h);
    }

    const int T = 256;
    const int nodeBlk = (nn + T - 1) / T;
    const int edgeBlk = (ne + T - 1) / T;
    const int gathBlk = (nn * 16 + T - 1) / T;
    const int gemmBlk = (nn + 127) / 128;
    const int scanNB  = (nn + SCAN_T - 1) / SCAN_T;

    // ---- one-time graph preprocessing: degrees, normalizers, dst-CSR ----
    zero_deg_kernel<<<nodeBlk, T>>>(nn);
    deg_kernel<<<edgeBlk, T>>>(src, dst, ne);
    inv_kernel<<<nodeBlk, T>>>(nn);
    scanA_kernel<<<scanNB, SCAN_T>>>(nn);
    scanB_kernel<<<1, 512>>>(scanNB);
    scanC_kernel<<<scanNB, SCAN_T>>>(nn);
    csr_fill_kernel<<<edgeBlk, T>>>(src, dst, ne);

    // ---- layer 1: x(128) -> h(64), relu ----
    gemm_mma_kernel<128><<<gemmBlk, 256>>>(x, W1, nn);
    gather_kernel<1><<<gathBlk, T>>>(b1, h_ptr, nn);

    // ---- layer 2: h(64) -> h(64), relu ----
    gemm_mma_kernel<64><<<gemmBlk, 256>>>(h_ptr, W2, nn);
    gather_kernel<1><<<gathBlk, T>>>(b2, h_ptr, nn);

    // ---- layer 3: h(64) -> out(64), no relu ----
    gemm_mma_kernel<64><<<gemmBlk, 256>>>(h_ptr, W3, nn);
    gather_kernel<0><<<gathBlk, T>>>(b3, out, nn);
}

// round 14
// speedup vs baseline: 1.4766x; 1.4766x over previous
#include <cuda_runtime.h>
#include <cuda_fp16.h>
#include <mma.h>

using namespace nvcuda;

// Problem constants (shapes fixed by the reference).
#define NMAX   100000
#define NEMAX  1600000
#define FEAT   64
#define SCAN_T 256

// ---------------- device scratch (no allocations allowed) ----------------
// g_t16 padded by 128 rows: last GEMM block stores a full 128-row tile unguarded.
__device__ __half   g_t16[(NMAX + 128) * FEAT];  // fp16 transformed features (gather input)
__device__ __half   g_h16[NMAX * FEAT];          // fp16 hidden activations
__device__ unsigned g_degout[NMAX];
__device__ unsigned g_degin[NMAX];
__device__ float    g_iso[NMAX];          // D_out^{-1/2}
__device__ float    g_isi[NMAX];          // D_in^{-1/2}
__device__ int      g_rowstart[NMAX + 1]; // CSR row offsets (by dst)
__device__ int      g_cursor[NMAX];       // fill cursors
__device__ int      g_csr[NEMAX];         // src ids grouped by dst
__device__ int      g_blksum[512];        // scan block totals

// ---------------- degree / normalizer kernels ----------------

__global__ void zero_deg_kernel(int nn) {
    int i = blockIdx.x * blockDim.x + threadIdx.x;
    if (i < nn) { g_degout[i] = 0u; g_degin[i] = 0u; g_cursor[i] = 0; }
    if (i == 0) g_rowstart[0] = 0;
}

__global__ void deg_kernel(const int* __restrict__ src, const int* __restrict__ dst, int ne) {
    int e = blockIdx.x * blockDim.x + threadIdx.x;
    if (e < ne) {
        atomicAdd(&g_degout[src[e]], 1u);
        atomicAdd(&g_degin[dst[e]], 1u);
    }
}

__global__ void inv_kernel(int nn) {
    int i = blockIdx.x * blockDim.x + threadIdx.x;
    if (i < nn) {
        g_iso[i] = rsqrtf(fmaxf((float)g_degout[i], 1.0f));
        g_isi[i] = rsqrtf(fmaxf((float)g_degin[i], 1.0f));
    }
}

// ---------------- prefix-sum (exclusive) over in-degrees -> g_rowstart ----------------
__global__ void scanA_kernel(int nn) {
    __shared__ int sh[SCAN_T];
    int tid = threadIdx.x;
    int i = blockIdx.x * SCAN_T + tid;
    int v = (i < nn) ? (int)g_degin[i] : 0;
    sh[tid] = v;
    __syncthreads();
#pragma unroll
    for (int off = 1; off < SCAN_T; off <<= 1) {
        int t = (tid >= off) ? sh[tid - off] : 0;
        __syncthreads();
        sh[tid] += t;
        __syncthreads();
    }
    if (i < nn) g_rowstart[i + 1] = sh[tid];
    if (tid == SCAN_T - 1) g_blksum[blockIdx.x] = sh[tid];
}

__global__ void scanB_kernel(int nb) {
    __shared__ int sh[512];
    int tid = threadIdx.x;
    sh[tid] = (tid < nb) ? g_blksum[tid] : 0;
    __syncthreads();
#pragma unroll
    for (int off = 1; off < 512; off <<= 1) {
        int t = (tid >= off) ? sh[tid - off] : 0;
        __syncthreads();
        sh[tid] += t;
        __syncthreads();
    }
    g_blksum[tid] = sh[tid];
}

__global__ void scanC_kernel(int nn) {
    int i = blockIdx.x * SCAN_T + threadIdx.x;
    if (i < nn && blockIdx.x > 0) g_rowstart[i + 1] += g_blksum[blockIdx.x - 1];
}

__global__ void csr_fill_kernel(const int* __restrict__ src, const int* __restrict__ dst, int ne) {
    int e = blockIdx.x * blockDim.x + threadIdx.x;
    if (e < ne) {
        int d = dst[e];
        int pos = atomicAdd(&g_cursor[d], 1);
        g_csr[g_rowstart[d] + pos] = src[e];
    }
}

// ---------------- dense transform via fp16 HMMA tensor cores ----------------
// T = (X * iso) @ W -> fp16 g_t16. Block: 128 rows x 64 cols, 256 threads (8 warps),
// warp = 32x32 subtile, m16n16k16 fragments, K chunked at 32 (2 k-steps/chunk).
// IN16: input rows are __half (layers 2,3); else fp32 (layer 1).
template <int K, bool IN16>
__global__ void gemm_mma_kernel(const void* __restrict__ Xv, const float* __restrict__ W, int nn) {
    constexpr int KC  = 32;
    constexpr int XLD = KC + 8;       // 40 halves (80 B rows; mult of 8 for wmma)
    constexpr int WLD = FEAT + 8;     // 72 halves
    constexpr int SLD = FEAT + 4;     // fp32 stage leading dim

    // Union: Ws (4.6KB) + Xs (10.2KB) vs fp32 stage tile (34.8KB).
    __shared__ __align__(16) char smem_raw[128 * SLD * sizeof(float)];
    __half (*Ws)[WLD] = reinterpret_cast<__half (*)[WLD]>(smem_raw);
    __half (*Xs)[XLD] = reinterpret_cast<__half (*)[XLD]>(smem_raw + KC * WLD * sizeof(__half));
    float  (*St)[SLD] = reinterpret_cast<float  (*)[SLD]>(smem_raw);

    const int tid = threadIdx.x;
    const int wid = tid >> 5;
    const int warp_row = wid >> 1;    // 0..3 -> 32-row band
    const int warp_col = wid & 1;     // 0..1 -> 32-col band
    const int nodeBase = blockIdx.x * 128;

    wmma::fragment<wmma::accumulator, 16, 16, 16, float> acc[2][2];
#pragma unroll
    for (int r = 0; r < 2; r++)
#pragma unroll
        for (int c = 0; c < 2; c++) wmma::fill_fragment(acc[r][c], 0.0f);

    for (int k0 = 0; k0 < K; k0 += KC) {
        // W chunk: KC x 64 fp32 -> fp16 smem. 4 cols per item; KC*16 = 512 items.
#pragma unroll
        for (int i = tid; i < KC * (FEAT / 4); i += 256) {
            int r = i >> 4, c4 = (i & 15) * 4;
            float4 v = *reinterpret_cast<const float4*>(&W[(k0 + r) * FEAT + c4]);
            __half2 h0 = __floats2half2_rn(v.x, v.y);
            __half2 h1 = __floats2half2_rn(v.z, v.w);
            uint2 pack;
            pack.x = *reinterpret_cast<unsigned*>(&h0);
            pack.y = *reinterpret_cast<unsigned*>(&h1);
            *reinterpret_cast<uint2*>(&Ws[r][c4]) = pack;
        }
        // X chunk: 128 x KC, iso-scaled, fp16 smem. 8 cols per item; 128*(KC/8)=512 items.
#pragma unroll
        for (int i = tid; i < 128 * (KC / 8); i += 256) {
            int r = i / (KC / 8), c8 = (i % (KC / 8)) * 8;
            int node = nodeBase + r;
            float f[8];
#pragma unroll
            for (int t = 0; t < 8; t++) f[t] = 0.f;
            if (node < nn) {
                float s = g_iso[node];
                if (IN16) {
                    const __half* row = reinterpret_cast<const __half*>(Xv) + (size_t)node * K + k0 + c8;
                    uint4 u = __ldg(reinterpret_cast<const uint4*>(row));
                    float2 a0 = __half22float2(*reinterpret_cast<__half2*>(&u.x));
                    float2 a1 = __half22float2(*reinterpret_cast<__half2*>(&u.y));
                    float2 a2 = __half22float2(*reinterpret_cast<__half2*>(&u.z));
                    float2 a3 = __half22float2(*reinterpret_cast<__half2*>(&u.w));
                    f[0] = a0.x * s; f[1] = a0.y * s; f[2] = a1.x * s; f[3] = a1.y * s;
                    f[4] = a2.x * s; f[5] = a2.y * s; f[6] = a3.x * s; f[7] = a3.y * s;
                } else {
                    const float* row = reinterpret_cast<const float*>(Xv) + (size_t)node * K + k0 + c8;
                    float4 v0 = __ldg(reinterpret_cast<const float4*>(row));
                    float4 v1 = __ldg(reinterpret_cast<const float4*>(row + 4));
                    f[0] = v0.x * s; f[1] = v0.y * s; f[2] = v0.z * s; f[3] = v0.w * s;
                    f[4] = v1.x * s; f[5] = v1.y * s; f[6] = v1.z * s; f[7] = v1.w * s;
                }
            }
            __half2 h0 = __floats2half2_rn(f[0], f[1]);
            __half2 h1 = __floats2half2_rn(f[2], f[3]);
            __half2 h2 = __floats2half2_rn(f[4], f[5]);
            __half2 h3 = __floats2half2_rn(f[6], f[7]);
            uint4 pack;
            pack.x = *reinterpret_cast<unsigned*>(&h0);
            pack.y = *reinterpret_cast<unsigned*>(&h1);
            pack.z = *reinterpret_cast<unsigned*>(&h2);
            pack.w = *reinterpret_cast<unsigned*>(&h3);
            *reinterpret_cast<uint4*>(&Xs[r][c8]) = pack;
        }
        __syncthreads();

#pragma unroll
        for (int kk = 0; kk < KC; kk += 16) {
            wmma::fragment<wmma::matrix_a, 16, 16, 16, __half, wmma::row_major> a[2];
            wmma::fragment<wmma::matrix_b, 16, 16, 16, __half, wmma::row_major> b[2];
#pragma unroll
            for (int r = 0; r < 2; r++)
                wmma::load_matrix_sync(a[r], &Xs[warp_row * 32 + r * 16][kk], XLD);
#pragma unroll
            for (int c = 0; c < 2; c++)
                wmma::load_matrix_sync(b[c], &Ws[kk][warp_col * 32 + c * 16], WLD);
#pragma unroll
            for (int r = 0; r < 2; r++)
#pragma unroll
                for (int c = 0; c < 2; c++)
                    wmma::mma_sync(acc[r][c], a[r], b[c], acc[r][c]);
        }
        __syncthreads();
    }

    // Epilogue: fp32 tile -> smem stage -> packed fp16 global stores.
#pragma unroll
    for (int r = 0; r < 2; r++)
#pragma unroll
        for (int c = 0; c < 2; c++)
            wmma::store_matrix_sync(&St[warp_row * 32 + r * 16][warp_col * 32 + c * 16],
                                    acc[r][c], SLD, wmma::mem_row_major);
    __syncthreads();

#pragma unroll
    for (int i = tid; i < 128 * (FEAT / 8); i += 256) {
        int r = i >> 3;
        int c8 = (i & 7) * 8;
        float4 f0 = *reinterpret_cast<float4*>(&St[r][c8]);
        float4 f1 = *reinterpret_cast<float4*>(&St[r][c8 + 4]);
        __half2 h0 = __floats2half2_rn(f0.x, f0.y);
        __half2 h1 = __floats2half2_rn(f0.z, f0.w);
        __half2 h2 = __floats2half2_rn(f1.x, f1.y);
        __half2 h3 = __floats2half2_rn(f1.z, f1.w);
        uint4 pack;
        pack.x = *reinterpret_cast<unsigned*>(&h0);
        pack.y = *reinterpret_cast<unsigned*>(&h1);
        pack.z = *reinterpret_cast<unsigned*>(&h2);
        pack.w = *reinterpret_cast<unsigned*>(&h3);
        *reinterpret_cast<uint4*>(&g_t16[(size_t)(nodeBase + r) * FEAT + c8]) = pack;
    }
}

// ---------------- CSR gather + finalize (R9 structure: per-lane loads, high MLP) ----------------
// 16 lanes per node; each lane owns 4 half columns (8 B per edge).
// OUT16: write fp16 hidden (layers 1,2); else fp32 final output.
template <int RELU, bool OUT16>
__global__ void gather_kernel(const float* __restrict__ b, void* __restrict__ outv, int nn) {
    int idx = blockIdx.x * blockDim.x + threadIdx.x;
    int node = idx >> 4;
    int c = (idx & 15) << 2;          // half-column base (0,4,...,60)
    if (node >= nn) return;

    int rs = g_rowstart[node];
    int re = g_rowstart[node + 1];

    float acc0 = 0.f, acc1 = 0.f, acc2 = 0.f, acc3 = 0.f;

#pragma unroll 4
    for (int p = rs; p < re; ++p) {
        int s = __ldg(&g_csr[p]);     // same addr across 16 lanes -> broadcast wavefront
        uint2 u = __ldg(reinterpret_cast<const uint2*>(&g_t16[(size_t)s * FEAT + c]));
        float2 f0 = __half22float2(*reinterpret_cast<__half2*>(&u.x));
        float2 f1 = __half22float2(*reinterpret_cast<__half2*>(&u.y));
        acc0 += f0.x; acc1 += f0.y; acc2 += f1.x; acc3 += f1.y;
    }

    float sN = g_isi[node];
    float4 bb = *reinterpret_cast<const float4*>(&b[c]);
    float o0 = acc0 * sN + bb.x;
    float o1 = acc1 * sN + bb.y;
    float o2 = acc2 * sN + bb.z;
    float o3 = acc3 * sN + bb.w;
    if (RELU) {
        o0 = fmaxf(o0, 0.f); o1 = fmaxf(o1, 0.f);
        o2 = fmaxf(o2, 0.f); o3 = fmaxf(o3, 0.f);
    }
    if (OUT16) {
        __half2 h0 = __floats2half2_rn(o0, o1);
        __half2 h1 = __floats2half2_rn(o2, o3);
        uint2 pack;
        pack.x = *reinterpret_cast<unsigned*>(&h0);
        pack.y = *reinterpret_cast<unsigned*>(&h1);
        *reinterpret_cast<uint2*>(reinterpret_cast<__half*>(outv) + (size_t)node * FEAT + c) = pack;
    } else {
        *reinterpret_cast<float4*>(reinterpret_cast<float*>(outv) + (size_t)node * FEAT + c) =
            make_float4(o0, o1, o2, o3);
    }
}

// ---------------- launch ----------------
extern "C" void kernel_launch(void* const* d_in, const int* in_sizes, int n_in,
                              void* d_out, int out_size) {
    const float* x   = (const float*)d_in[0];
    const int*   src = (const int*)d_in[1];
    const int*   dst = (const int*)d_in[2];
    const float* W1  = (const float*)d_in[3];
    const float* b1  = (const float*)d_in[4];
    const float* W2  = (const float*)d_in[5];
    const float* b2  = (const float*)d_in[6];
    const float* W3  = (const float*)d_in[7];
    const float* b3  = (const float*)d_in[8];

    const int nn = in_sizes[0] / 128;   // 100000
    const int ne = in_sizes[1];         // 1600000

    static __half* h16_ptr = nullptr;
    if (h16_ptr == nullptr) {
        cudaGetSymbolAddress((void**)&h16_ptr, g_h16);
    }

    const int T = 256;
    const int nodeBlk = (nn + T - 1) / T;
    const int edgeBlk = (ne + T - 1) / T;
    const int gathBlk = (nn * 16 + T - 1) / T;
    const int gemmBlk = (nn + 127) / 128;
    const int scanNB  = (nn + SCAN_T - 1) / SCAN_T;

    // ---- one-time graph preprocessing: degrees, normalizers, dst-CSR ----
    zero_deg_kernel<<<nodeBlk, T>>>(nn);
    deg_kernel<<<edgeBlk, T>>>(src, dst, ne);
    inv_kernel<<<nodeBlk, T>>>(nn);
    scanA_kernel<<<scanNB, SCAN_T>>>(nn);
    scanB_kernel<<<1, 512>>>(scanNB);
    scanC_kernel<<<scanNB, SCAN_T>>>(nn);
    csr_fill_kernel<<<edgeBlk, T>>>(src, dst, ne);

    // ---- layer 1: x(128, fp32) -> h16(64), relu ----
    gemm_mma_kernel<128, false><<<gemmBlk, 256>>>(x, W1, nn);
    gather_kernel<1, true><<<gathBlk, T>>>(b1, h16_ptr, nn);

    // ---- layer 2: h16(64) -> h16(64), relu ----
    gemm_mma_kernel<64, true><<<gemmBlk, 256>>>(h16_ptr, W2, nn);
    gather_kernel<1, true><<<gathBlk, T>>>(b2, h16_ptr, nn);

    // ---- layer 3: h16(64) -> out(64, fp32), no relu ----
    gemm_mma_kernel<64, true><<<gemmBlk, 256>>>(h16_ptr, W3, nn);
    gather_kernel<0, false><<<gathBlk, T>>>(b3, d_out, nn);
}

// round 15
// speedup vs baseline: 1.5512x; 1.0506x over previous
#include <cuda_runtime.h>
#include <cuda_fp16.h>
#include <mma.h>

using namespace nvcuda;

// Problem constants (shapes fixed by the reference).
#define NMAX   100000
#define NEMAX  1600000
#define FEAT   64
#define SCAN_T 256

// ---------------- device scratch (no allocations allowed) ----------------
// g_t16 padded by 128 rows: last GEMM block stores a full 128-row tile unguarded.
__device__ __half   g_t16[(NMAX + 128) * FEAT];  // fp16 transformed features (gather input)
__device__ __half   g_h16[NMAX * FEAT];          // fp16 hidden activations
__device__ unsigned g_degout[NMAX];
__device__ unsigned g_degin[NMAX];
__device__ float    g_iso[NMAX];          // D_out^{-1/2}
__device__ float    g_isi[NMAX];          // D_in^{-1/2}
__device__ int      g_rowstart[NMAX + 1]; // CSR row offsets (by dst)
__device__ int      g_cursor[NMAX];       // fill cursors
__device__ int      g_csr[NEMAX];         // src ids grouped by dst
__device__ int      g_blksum[512];        // scan block totals

// ---------------- degree / normalizer kernels ----------------

__global__ void zero_deg_kernel(int nn) {
    int i = blockIdx.x * blockDim.x + threadIdx.x;
    if (i < nn) { g_degout[i] = 0u; g_degin[i] = 0u; g_cursor[i] = 0; }
    if (i == 0) g_rowstart[0] = 0;
}

__global__ void deg_kernel(const int* __restrict__ src, const int* __restrict__ dst, int ne) {
    int e = blockIdx.x * blockDim.x + threadIdx.x;
    if (e < ne) {
        atomicAdd(&g_degout[src[e]], 1u);
        atomicAdd(&g_degin[dst[e]], 1u);
    }
}

__global__ void inv_kernel(int nn) {
    int i = blockIdx.x * blockDim.x + threadIdx.x;
    if (i < nn) {
        g_iso[i] = rsqrtf(fmaxf((float)g_degout[i], 1.0f));
        g_isi[i] = rsqrtf(fmaxf((float)g_degin[i], 1.0f));
    }
}

// ---------------- prefix-sum (exclusive) over in-degrees -> g_rowstart ----------------
__global__ void scanA_kernel(int nn) {
    __shared__ int sh[SCAN_T];
    int tid = threadIdx.x;
    int i = blockIdx.x * SCAN_T + tid;
    int v = (i < nn) ? (int)g_degin[i] : 0;
    sh[tid] = v;
    __syncthreads();
#pragma unroll
    for (int off = 1; off < SCAN_T; off <<= 1) {
        int t = (tid >= off) ? sh[tid - off] : 0;
        __syncthreads();
        sh[tid] += t;
        __syncthreads();
    }
    if (i < nn) g_rowstart[i + 1] = sh[tid];
    if (tid == SCAN_T - 1) g_blksum[blockIdx.x] = sh[tid];
}

__global__ void scanB_kernel(int nb) {
    __shared__ int sh[512];
    int tid = threadIdx.x;
    sh[tid] = (tid < nb) ? g_blksum[tid] : 0;
    __syncthreads();
#pragma unroll
    for (int off = 1; off < 512; off <<= 1) {
        int t = (tid >= off) ? sh[tid - off] : 0;
        __syncthreads();
        sh[tid] += t;
        __syncthreads();
    }
    g_blksum[tid] = sh[tid];
}

__global__ void scanC_kernel(int nn) {
    int i = blockIdx.x * SCAN_T + threadIdx.x;
    if (i < nn && blockIdx.x > 0) g_rowstart[i + 1] += g_blksum[blockIdx.x - 1];
}

__global__ void csr_fill_kernel(const int* __restrict__ src, const int* __restrict__ dst, int ne) {
    int e = blockIdx.x * blockDim.x + threadIdx.x;
    if (e < ne) {
        int d = dst[e];
        int pos = atomicAdd(&g_cursor[d], 1);
        g_csr[g_rowstart[d] + pos] = src[e];
    }
}

// ---------------- dense transform via fp16 HMMA tensor cores ----------------
// T = (X * iso) @ W -> fp16 g_t16. Block: 128 rows x 64 cols, 256 threads (8 warps),
// warp = 32x32 subtile, m16n16k16 fragments, K chunked at 32 (2 k-steps/chunk).
// IN16: input rows are __half (layers 2,3); else fp32 (layer 1).
template <int K, bool IN16>
__global__ void gemm_mma_kernel(const void* __restrict__ Xv, const float* __restrict__ W, int nn) {
    constexpr int KC  = 32;
    constexpr int XLD = KC + 8;       // 40 halves (80 B rows; mult of 8 for wmma)
    constexpr int WLD = FEAT + 8;     // 72 halves
    constexpr int SLD = FEAT + 4;     // fp32 stage leading dim

    // Union: Ws (4.6KB) + Xs (10.2KB) vs fp32 stage tile (34.8KB).
    __shared__ __align__(16) char smem_raw[128 * SLD * sizeof(float)];
    __half (*Ws)[WLD] = reinterpret_cast<__half (*)[WLD]>(smem_raw);
    __half (*Xs)[XLD] = reinterpret_cast<__half (*)[XLD]>(smem_raw + KC * WLD * sizeof(__half));
    float  (*St)[SLD] = reinterpret_cast<float  (*)[SLD]>(smem_raw);

    const int tid = threadIdx.x;
    const int wid = tid >> 5;
    const int warp_row = wid >> 1;    // 0..3 -> 32-row band
    const int warp_col = wid & 1;     // 0..1 -> 32-col band
    const int nodeBase = blockIdx.x * 128;

    wmma::fragment<wmma::accumulator, 16, 16, 16, float> acc[2][2];
#pragma unroll
    for (int r = 0; r < 2; r++)
#pragma unroll
        for (int c = 0; c < 2; c++) wmma::fill_fragment(acc[r][c], 0.0f);

    for (int k0 = 0; k0 < K; k0 += KC) {
        // W chunk: KC x 64 fp32 -> fp16 smem. 4 cols per item; KC*16 = 512 items.
#pragma unroll
        for (int i = tid; i < KC * (FEAT / 4); i += 256) {
            int r = i >> 4, c4 = (i & 15) * 4;
            float4 v = *reinterpret_cast<const float4*>(&W[(k0 + r) * FEAT + c4]);
            __half2 h0 = __floats2half2_rn(v.x, v.y);
            __half2 h1 = __floats2half2_rn(v.z, v.w);
            uint2 pack;
            pack.x = *reinterpret_cast<unsigned*>(&h0);
            pack.y = *reinterpret_cast<unsigned*>(&h1);
            *reinterpret_cast<uint2*>(&Ws[r][c4]) = pack;
        }
        // X chunk: 128 x KC, iso-scaled, fp16 smem. 8 cols per item; 128*(KC/8)=512 items.
#pragma unroll
        for (int i = tid; i < 128 * (KC / 8); i += 256) {
            int r = i / (KC / 8), c8 = (i % (KC / 8)) * 8;
            int node = nodeBase + r;
            float f[8];
#pragma unroll
            for (int t = 0; t < 8; t++) f[t] = 0.f;
            if (node < nn) {
                float s = g_iso[node];
                if (IN16) {
                    const __half* row = reinterpret_cast<const __half*>(Xv) + (size_t)node * K + k0 + c8;
                    uint4 u = __ldg(reinterpret_cast<const uint4*>(row));
                    float2 a0 = __half22float2(*reinterpret_cast<__half2*>(&u.x));
                    float2 a1 = __half22float2(*reinterpret_cast<__half2*>(&u.y));
                    float2 a2 = __half22float2(*reinterpret_cast<__half2*>(&u.z));
                    float2 a3 = __half22float2(*reinterpret_cast<__half2*>(&u.w));
                    f[0] = a0.x * s; f[1] = a0.y * s; f[2] = a1.x * s; f[3] = a1.y * s;
                    f[4] = a2.x * s; f[5] = a2.y * s; f[6] = a3.x * s; f[7] = a3.y * s;
                } else {
                    const float* row = reinterpret_cast<const float*>(Xv) + (size_t)node * K + k0 + c8;
                    float4 v0 = __ldg(reinterpret_cast<const float4*>(row));
                    float4 v1 = __ldg(reinterpret_cast<const float4*>(row + 4));
                    f[0] = v0.x * s; f[1] = v0.y * s; f[2] = v0.z * s; f[3] = v0.w * s;
                    f[4] = v1.x * s; f[5] = v1.y * s; f[6] = v1.z * s; f[7] = v1.w * s;
                }
            }
            __half2 h0 = __floats2half2_rn(f[0], f[1]);
            __half2 h1 = __floats2half2_rn(f[2], f[3]);
            __half2 h2 = __floats2half2_rn(f[4], f[5]);
            __half2 h3 = __floats2half2_rn(f[6], f[7]);
            uint4 pack;
            pack.x = *reinterpret_cast<unsigned*>(&h0);
            pack.y = *reinterpret_cast<unsigned*>(&h1);
            pack.z = *reinterpret_cast<unsigned*>(&h2);
            pack.w = *reinterpret_cast<unsigned*>(&h3);
            *reinterpret_cast<uint4*>(&Xs[r][c8]) = pack;
        }
        __syncthreads();

#pragma unroll
        for (int kk = 0; kk < KC; kk += 16) {
            wmma::fragment<wmma::matrix_a, 16, 16, 16, __half, wmma::row_major> a[2];
            wmma::fragment<wmma::matrix_b, 16, 16, 16, __half, wmma::row_major> b[2];
#pragma unroll
            for (int r = 0; r < 2; r++)
                wmma::load_matrix_sync(a[r], &Xs[warp_row * 32 + r * 16][kk], XLD);
#pragma unroll
            for (int c = 0; c < 2; c++)
                wmma::load_matrix_sync(b[c], &Ws[kk][warp_col * 32 + c * 16], WLD);
#pragma unroll
            for (int r = 0; r < 2; r++)
#pragma unroll
                for (int c = 0; c < 2; c++)
                    wmma::mma_sync(acc[r][c], a[r], b[c], acc[r][c]);
        }
        __syncthreads();
    }

    // Epilogue: fp32 tile -> smem stage -> packed fp16 global stores.
#pragma unroll
    for (int r = 0; r < 2; r++)
#pragma unroll
        for (int c = 0; c < 2; c++)
            wmma::store_matrix_sync(&St[warp_row * 32 + r * 16][warp_col * 32 + c * 16],
                                    acc[r][c], SLD, wmma::mem_row_major);
    __syncthreads();

#pragma unroll
    for (int i = tid; i < 128 * (FEAT / 8); i += 256) {
        int r = i >> 3;
        int c8 = (i & 7) * 8;
        float4 f0 = *reinterpret_cast<float4*>(&St[r][c8]);
        float4 f1 = *reinterpret_cast<float4*>(&St[r][c8 + 4]);
        __half2 h0 = __floats2half2_rn(f0.x, f0.y);
        __half2 h1 = __floats2half2_rn(f0.z, f0.w);
        __half2 h2 = __floats2half2_rn(f1.x, f1.y);
        __half2 h3 = __floats2half2_rn(f1.z, f1.w);
        uint4 pack;
        pack.x = *reinterpret_cast<unsigned*>(&h0);
        pack.y = *reinterpret_cast<unsigned*>(&h1);
        pack.z = *reinterpret_cast<unsigned*>(&h2);
        pack.w = *reinterpret_cast<unsigned*>(&h3);
        *reinterpret_cast<uint4*>(&g_t16[(size_t)(nodeBase + r) * FEAT + c8]) = pack;
    }
}

// ---------------- CSR gather + finalize (per-lane loads, high MLP) ----------------
// 16 lanes per node; each lane owns 4 half columns (8 B per edge).
// OUT16: write fp16 hidden (layers 1,2); else fp32 final output.
template <int RELU, bool OUT16>
__global__ void gather_kernel(const float* __restrict__ b, void* __restrict__ outv, int nn) {
    int idx = blockIdx.x * blockDim.x + threadIdx.x;
    int node = idx >> 4;
    int c = (idx & 15) << 2;          // half-column base (0,4,...,60)
    if (node >= nn) return;

    int rs = g_rowstart[node];
    int re = g_rowstart[node + 1];

    float acc0 = 0.f, acc1 = 0.f, acc2 = 0.f, acc3 = 0.f;

#pragma unroll 4
    for (int p = rs; p < re; ++p) {
        int s = __ldg(&g_csr[p]);     // same addr across 16 lanes -> broadcast wavefront
        uint2 u = __ldg(reinterpret_cast<const uint2*>(&g_t16[(size_t)s * FEAT + c]));
        float2 f0 = __half22float2(*reinterpret_cast<__half2*>(&u.x));
        float2 f1 = __half22float2(*reinterpret_cast<__half2*>(&u.y));
        acc0 += f0.x; acc1 += f0.y; acc2 += f1.x; acc3 += f1.y;
    }

    float sN = g_isi[node];
    float4 bb = *reinterpret_cast<const float4*>(&b[c]);
    float o0 = acc0 * sN + bb.x;
    float o1 = acc1 * sN + bb.y;
    float o2 = acc2 * sN + bb.z;
    float o3 = acc3 * sN + bb.w;
    if (RELU) {
        o0 = fmaxf(o0, 0.f); o1 = fmaxf(o1, 0.f);
        o2 = fmaxf(o2, 0.f); o3 = fmaxf(o3, 0.f);
    }
    if (OUT16) {
        __half2 h0 = __floats2half2_rn(o0, o1);
        __half2 h1 = __floats2half2_rn(o2, o3);
        uint2 pack;
        pack.x = *reinterpret_cast<unsigned*>(&h0);
        pack.y = *reinterpret_cast<unsigned*>(&h1);
        *reinterpret_cast<uint2*>(reinterpret_cast<__half*>(outv) + (size_t)node * FEAT + c) = pack;
    } else {
        *reinterpret_cast<float4*>(reinterpret_cast<float*>(outv) + (size_t)node * FEAT + c) =
            make_float4(o0, o1, o2, o3);
    }
}

// ---------------- launch ----------------
extern "C" void kernel_launch(void* const* d_in, const int* in_sizes, int n_in,
                              void* d_out, int out_size) {
    const float* x   = (const float*)d_in[0];
    const int*   src = (const int*)d_in[1];
    const int*   dst = (const int*)d_in[2];
    const float* W1  = (const float*)d_in[3];
    const float* b1  = (const float*)d_in[4];
    const float* W2  = (const float*)d_in[5];
    const float* b2  = (const float*)d_in[6];
    const float* W3  = (const float*)d_in[7];
    const float* b3  = (const float*)d_in[8];

    const int nn = in_sizes[0] / 128;   // 100000
    const int ne = in_sizes[1];         // 1600000

    // One-time setup (first call is the uncaptured correctness run).
    static __half* h16_ptr = nullptr;
    static cudaStream_t s_side = nullptr;
    static cudaEvent_t ev_fork = nullptr, ev_join = nullptr;
    if (h16_ptr == nullptr) {
        cudaGetSymbolAddress((void**)&h16_ptr, g_h16);
        cudaStreamCreateWithFlags(&s_side, cudaStreamNonBlocking);
        cudaEventCreateWithFlags(&ev_fork, cudaEventDisableTiming);
        cudaEventCreateWithFlags(&ev_join, cudaEventDisableTiming);
    }

    const int T = 256;
    const int nodeBlk = (nn + T - 1) / T;
    const int edgeBlk = (ne + T - 1) / T;
    const int gathBlk = (nn * 16 + T - 1) / T;
    const int gemmBlk = (nn + 127) / 128;
    const int scanNB  = (nn + SCAN_T - 1) / SCAN_T;

    // ---- shared prerequisites: degrees + normalizers (main stream) ----
    zero_deg_kernel<<<nodeBlk, T>>>(nn);
    deg_kernel<<<edgeBlk, T>>>(src, dst, ne);
    inv_kernel<<<nodeBlk, T>>>(nn);

    // ---- fork: gemm1 (needs iso only) runs concurrently with CSR build ----
    cudaEventRecord(ev_fork, 0);
    cudaStreamWaitEvent(s_side, ev_fork, 0);
    gemm_mma_kernel<128, false><<<gemmBlk, 256, 0, s_side>>>(x, W1, nn);
    cudaEventRecord(ev_join, s_side);

    scanA_kernel<<<scanNB, SCAN_T>>>(nn);
    scanB_kernel<<<1, 512>>>(scanNB);
    scanC_kernel<<<scanNB, SCAN_T>>>(nn);
    csr_fill_kernel<<<edgeBlk, T>>>(src, dst, ne);

    // ---- join: gather1 needs both CSR (main) and t16 (side) ----
    cudaStreamWaitEvent(0, ev_join, 0);
    gather_kernel<1, true><<<gathBlk, T>>>(b1, h16_ptr, nn);

    // ---- layer 2: h16(64) -> h16(64), relu ----
    gemm_mma_kernel<64, true><<<gemmBlk, 256>>>(h16_ptr, W2, nn);
    gather_kernel<1, true><<<gathBlk, T>>>(b2, h16_ptr, nn);

    // ---- layer 3: h16(64) -> out(64, fp32), no relu ----
    gemm_mma_kernel<64, true><<<gemmBlk, 256>>>(h16_ptr, W3, nn);
    gather_kernel<0, false><<<gathBlk, T>>>(b3, d_out, nn);
}